// round 5
// baseline (speedup 1.0000x reference)
#include <cuda_runtime.h>
#include <cuda_bf16.h>
#include <math.h>

// Problem constants (fixed by the dataset)
#define NN 100000
#define EE 200000
#define BB 2048
#define DD 256
#define LL 5

// ---------------- scratch (device globals; no allocation allowed) ----------
__device__ float g_h[(size_t)NN * DD];        // node features
__device__ float g_agg[(size_t)NN * DD];      // aggregated features
__device__ float g_z1[(size_t)NN * 2 * DD];   // MLP hidden (N x 512)
__device__ float g_z[(size_t)NN * DD];        // MLP output pre-BN
__device__ float g_stats[2 * DD];             // column sums / sums of squares
__device__ float g_pooled[(size_t)BB * DD];
__device__ int   g_cnt[BB];

// ---------------- embed: h = x_emb1[x[:,0]] + x_emb2[x[:,1]] ----------------
__global__ void embed_kernel(const int* __restrict__ x,
                             const float* __restrict__ e1,
                             const float* __restrict__ e2,
                             float* __restrict__ h, int n)
{
    int idx = blockIdx.x * blockDim.x + threadIdx.x;
    int total = n * DD;
    if (idx >= total) return;
    int row = idx / DD;
    int d = idx - row * DD;
    int a = x[row * 2];
    int c = x[row * 2 + 1];
    h[idx] = e1[(size_t)a * DD + d] + e2[(size_t)c * DD + d];
}

// ---------------- init agg = h + self_e; also zero BN stats ----------------
__global__ void init_agg_kernel(const float* __restrict__ h,
                                const float* __restrict__ e1l,   // edge_emb1[l] (5 x D)
                                const float* __restrict__ e2l,   // edge_emb2[l] (3 x D)
                                float* __restrict__ agg,
                                float* __restrict__ stats, int n)
{
    int idx = blockIdx.x * blockDim.x + threadIdx.x;
    if (idx < 2 * DD) stats[idx] = 0.0f;
    int total = n * DD;
    if (idx >= total) return;
    int d = idx & (DD - 1);
    float self_e = e1l[4 * DD + d] + e2l[d];
    agg[idx] = h[idx] + self_e;
}

// ---------------- scatter: agg[dst] += h[src] + e(bt,bd)  (warp per edge) ---
__global__ void scatter_kernel(const int* __restrict__ ei,
                               const int* __restrict__ ea,
                               const float* __restrict__ e1l,
                               const float* __restrict__ e2l,
                               const float* __restrict__ h,
                               float* __restrict__ agg, int e_cnt)
{
    int gw = (blockIdx.x * blockDim.x + threadIdx.x) >> 5;
    int lane = threadIdx.x & 31;
    if (gw >= e_cnt) return;
    int src = ei[gw];
    int dst = ei[e_cnt + gw];
    int bt = ea[2 * gw];
    int bd = ea[2 * gw + 1];
    const float* hv = h + (size_t)src * DD;
    const float* t1 = e1l + (size_t)bt * DD;
    const float* t2 = e2l + (size_t)bd * DD;
    float* av = agg + (size_t)dst * DD;
#pragma unroll
    for (int d = lane; d < DD; d += 32) {
        atomicAdd(&av[d], hv[d] + t1[d] + t2[d]);
    }
}

// ---------------- tiled fp32 SGEMM: C = act(A @ B + bias) -------------------
// A: M x K row-major, B: K x Nc row-major, C: M x Nc. 256 threads/block.
#define GBM 128
#define GBN 128
#define GBK 8
#define GTM 8
#define GTN 8

template<bool RELU>
__global__ __launch_bounds__(256, 2)
void sgemm_kernel(int M, int Nc, int K,
                  const float* __restrict__ A,
                  const float* __restrict__ B,
                  const float* __restrict__ bias,
                  float* __restrict__ C)
{
    __shared__ float As[GBK][GBM];
    __shared__ float Bs[GBK][GBN];

    const int cRow = blockIdx.y;
    const int cCol = blockIdx.x;
    const int tid = threadIdx.x;

    const int tCol = tid % (GBN / GTN);   // 0..15
    const int tRow = tid / (GBN / GTN);   // 0..15

    const int aRow = tid >> 1;            // 0..127
    const int aCol = (tid & 1) * 4;       // 0 or 4
    const int bRow = tid >> 5;            // 0..7
    const int bCol = (tid & 31) * 4;      // 0..124

    float acc[GTM][GTN];
#pragma unroll
    for (int i = 0; i < GTM; i++)
#pragma unroll
        for (int j = 0; j < GTN; j++) acc[i][j] = 0.0f;

    float regM[GTM], regN[GTN];

    const int gARow = cRow * GBM + aRow;
    const float* Aptr = A + (size_t)gARow * K;
    const float* Bptr = B + (size_t)bRow * Nc + cCol * GBN + bCol;

    for (int k0 = 0; k0 < K; k0 += GBK) {
        float4 av = (gARow < M)
            ? *reinterpret_cast<const float4*>(Aptr + k0 + aCol)
            : make_float4(0.f, 0.f, 0.f, 0.f);
        As[aCol + 0][aRow] = av.x;
        As[aCol + 1][aRow] = av.y;
        As[aCol + 2][aRow] = av.z;
        As[aCol + 3][aRow] = av.w;

        float4 bv = *reinterpret_cast<const float4*>(Bptr + (size_t)k0 * Nc);
        *reinterpret_cast<float4*>(&Bs[bRow][bCol]) = bv;

        __syncthreads();
#pragma unroll
        for (int k = 0; k < GBK; k++) {
#pragma unroll
            for (int i = 0; i < GTM; i++) regM[i] = As[k][tRow * GTM + i];
#pragma unroll
            for (int j = 0; j < GTN; j++) regN[j] = Bs[k][tCol * GTN + j];
#pragma unroll
            for (int i = 0; i < GTM; i++)
#pragma unroll
                for (int j = 0; j < GTN; j++)
                    acc[i][j] = fmaf(regM[i], regN[j], acc[i][j]);
        }
        __syncthreads();
    }

#pragma unroll
    for (int i = 0; i < GTM; i++) {
        int gRow = cRow * GBM + tRow * GTM + i;
        if (gRow >= M) continue;
        float* Crow = C + (size_t)gRow * Nc + cCol * GBN;
#pragma unroll
        for (int j = 0; j < GTN; j += 4) {
            int col = tCol * GTN + j;
            float4 v;
            v.x = acc[i][j + 0] + bias[cCol * GBN + col + 0];
            v.y = acc[i][j + 1] + bias[cCol * GBN + col + 1];
            v.z = acc[i][j + 2] + bias[cCol * GBN + col + 2];
            v.w = acc[i][j + 3] + bias[cCol * GBN + col + 3];
            if (RELU) {
                v.x = fmaxf(v.x, 0.f); v.y = fmaxf(v.y, 0.f);
                v.z = fmaxf(v.z, 0.f); v.w = fmaxf(v.w, 0.f);
            }
            *reinterpret_cast<float4*>(Crow + col) = v;
        }
    }
}

// ---------------- BN column stats: sums / sumsq per column ------------------
__global__ void stats_kernel(const float* __restrict__ z,
                             float* __restrict__ stats, int n)
{
    int d = threadIdx.x;   // 256 threads = 256 columns
    float s = 0.f, s2 = 0.f;
    for (int r = blockIdx.x; r < n; r += gridDim.x) {
        float v = z[(size_t)r * DD + d];
        s += v;
        s2 += v * v;
    }
    atomicAdd(&stats[d], s);
    atomicAdd(&stats[DD + d], s2);
}

// ---------------- BN normalize + relu -> h ---------------------------------
__global__ void bn_relu_kernel(const float* __restrict__ z,
                               const float* __restrict__ stats,
                               const float* __restrict__ g,
                               const float* __restrict__ b,
                               float* __restrict__ h, int n)
{
    int idx = blockIdx.x * blockDim.x + threadIdx.x;
    int total = n * DD;
    if (idx >= total) return;
    int d = idx & (DD - 1);
    float invn = 1.0f / (float)n;
    float mu = stats[d] * invn;
    float var = stats[DD + d] * invn - mu * mu;
    float inv = rsqrtf(var + 1e-5f);
    float v = (z[idx] - mu) * inv * g[d] + b[d];
    h[idx] = fmaxf(v, 0.f);
}

// ---------------- pooling ---------------------------------------------------
__global__ void zero_pool_kernel(float* __restrict__ pooled, int* __restrict__ cnt)
{
    int idx = blockIdx.x * blockDim.x + threadIdx.x;
    if (idx < BB * DD) pooled[idx] = 0.f;
    if (idx < BB) cnt[idx] = 0;
}

__global__ void pool_cnt_kernel(const int* __restrict__ batch, int* __restrict__ cnt, int n)
{
    int i = blockIdx.x * blockDim.x + threadIdx.x;
    if (i < n) atomicAdd(&cnt[batch[i]], 1);
}

__global__ void pool_sum_kernel(const float* __restrict__ h,
                                const int* __restrict__ batch,
                                float* __restrict__ pooled, int n)
{
    int idx = blockIdx.x * blockDim.x + threadIdx.x;
    int total = n * DD;
    if (idx >= total) return;
    int row = idx / DD;
    int d = idx - row * DD;
    int g = batch[row];
    atomicAdd(&pooled[(size_t)g * DD + d], h[idx]);
}

// ---------------- head: softplus(pooled/cnt @ Wo1 + bo1) @ Wo2 + bo2 --------
__global__ void head_kernel(const float* __restrict__ pooled,
                            const int* __restrict__ cnt,
                            const float* __restrict__ Wo1,
                            const float* __restrict__ bo1,
                            const float* __restrict__ Wo2,
                            const float* __restrict__ bo2,
                            float* __restrict__ out)
{
    __shared__ float p[DD];
    __shared__ float r0[128];
    __shared__ float r1[128];
    int g = blockIdx.x;
    int t = threadIdx.x;   // 128 threads
    float inv = 1.0f / fmaxf((float)cnt[g], 1.0f);
    p[t]        = pooled[(size_t)g * DD + t] * inv;
    p[t + 128]  = pooled[(size_t)g * DD + t + 128] * inv;
    __syncthreads();

    float acc = bo1[t];
#pragma unroll 8
    for (int k = 0; k < DD; k++)
        acc = fmaf(p[k], Wo1[k * 128 + t], acc);

    // numerically-stable softplus
    float sp = (acc > 0.f) ? (acc + log1pf(expf(-acc))) : log1pf(expf(acc));

    r0[t] = sp * Wo2[t * 2 + 0];
    r1[t] = sp * Wo2[t * 2 + 1];
    __syncthreads();
    for (int s = 64; s > 0; s >>= 1) {
        if (t < s) { r0[t] += r0[t + s]; r1[t] += r1[t + s]; }
        __syncthreads();
    }
    if (t == 0) {
        out[g * 2 + 0] = r0[0] + bo2[0];
        out[g * 2 + 1] = r1[0] + bo2[1];
    }
}

// ---------------- launch ----------------------------------------------------
extern "C" void kernel_launch(void* const* d_in, const int* in_sizes, int n_in,
                              void* d_out, int out_size)
{
    const int*   x         = (const int*)d_in[0];
    const int*   ei        = (const int*)d_in[1];
    const int*   ea        = (const int*)d_in[2];
    const int*   batch     = (const int*)d_in[3];
    const float* x_emb1    = (const float*)d_in[4];
    const float* x_emb2    = (const float*)d_in[5];
    const float* edge_emb1 = (const float*)d_in[6];   // (5, 5, 256)
    const float* edge_emb2 = (const float*)d_in[7];   // (5, 3, 256)
    const float* W1        = (const float*)d_in[8];   // (5, 256, 512)
    const float* b1        = (const float*)d_in[9];   // (5, 512)
    const float* W2        = (const float*)d_in[10];  // (5, 512, 256)
    const float* b2        = (const float*)d_in[11];  // (5, 256)
    const float* bn_g      = (const float*)d_in[12];  // (5, 256)
    const float* bn_b      = (const float*)d_in[13];  // (5, 256)
    const float* Wo1       = (const float*)d_in[14];  // (256, 128)
    const float* bo1       = (const float*)d_in[15];
    const float* Wo2       = (const float*)d_in[16];  // (128, 2)
    const float* bo2       = (const float*)d_in[17];
    float* out = (float*)d_out;

    const int n = in_sizes[0] / 2;   // 100000
    const int e = in_sizes[1] / 2;   // 200000

    float* h      = nullptr;
    float* agg    = nullptr;
    float* z1     = nullptr;
    float* z      = nullptr;
    float* stats  = nullptr;
    float* pooled = nullptr;
    int*   cnt    = nullptr;
    cudaGetSymbolAddress((void**)&h,      g_h);
    cudaGetSymbolAddress((void**)&agg,    g_agg);
    cudaGetSymbolAddress((void**)&z1,     g_z1);
    cudaGetSymbolAddress((void**)&z,      g_z);
    cudaGetSymbolAddress((void**)&stats,  g_stats);
    cudaGetSymbolAddress((void**)&pooled, g_pooled);
    cudaGetSymbolAddress((void**)&cnt,    g_cnt);

    const int TPB = 256;
    const int totND = n * DD;
    const int gND = (totND + TPB - 1) / TPB;

    embed_kernel<<<gND, TPB>>>(x, x_emb1, x_emb2, h, n);

    for (int l = 0; l < LL; l++) {
        const float* e1l = edge_emb1 + (size_t)l * 5 * DD;
        const float* e2l = edge_emb2 + (size_t)l * 3 * DD;
        const float* W1l = W1 + (size_t)l * DD * 2 * DD;
        const float* b1l = b1 + (size_t)l * 2 * DD;
        const float* W2l = W2 + (size_t)l * 2 * DD * DD;
        const float* b2l = b2 + (size_t)l * DD;
        const float* gl  = bn_g + (size_t)l * DD;
        const float* bl  = bn_b + (size_t)l * DD;

        init_agg_kernel<<<gND, TPB>>>(h, e1l, e2l, agg, stats, n);

        int scatterBlocks = (e * 32 + TPB - 1) / TPB;
        scatter_kernel<<<scatterBlocks, TPB>>>(ei, ea, e1l, e2l, h, agg, e);

        // GEMM1: z1 = relu(agg @ W1l + b1l)   (n x 512)
        {
            dim3 grid(2 * DD / GBN, (n + GBM - 1) / GBM);
            sgemm_kernel<true><<<grid, 256>>>(n, 2 * DD, DD, agg, W1l, b1l, z1);
        }
        // GEMM2: z = z1 @ W2l + b2l           (n x 256)
        {
            dim3 grid(DD / GBN, (n + GBM - 1) / GBM);
            sgemm_kernel<false><<<grid, 256>>>(n, DD, 2 * DD, z1, W2l, b2l, z);
        }

        stats_kernel<<<512, DD>>>(z, stats, n);
        bn_relu_kernel<<<gND, TPB>>>(z, stats, gl, bl, h, n);
    }

    zero_pool_kernel<<<(BB * DD + TPB - 1) / TPB, TPB>>>(pooled, cnt);
    pool_cnt_kernel<<<(n + TPB - 1) / TPB, TPB>>>(batch, cnt, n);
    pool_sum_kernel<<<gND, TPB>>>(h, batch, pooled, n);
    head_kernel<<<BB, 128>>>(pooled, cnt, Wo1, bo1, Wo2, bo2, out);
}

// round 6
// speedup vs baseline: 2.1030x; 2.1030x over previous
#include <cuda_runtime.h>
#include <cuda_bf16.h>
#include <math.h>

// Problem constants (fixed by the dataset)
#define NN 100000
#define EE 200000
#define BB 2048
#define DD 256
#define LL 5

// ---------------- scratch (device globals; no allocation allowed) ----------
__device__ float g_h[(size_t)NN * DD];        // node features
__device__ float g_agg[(size_t)NN * DD];      // aggregated features
__device__ float g_z1[(size_t)NN * 2 * DD];   // MLP hidden (N x 512)
__device__ float g_z[(size_t)NN * DD];        // MLP output pre-BN
__device__ float g_stats[2 * DD];             // column sums / sums of squares
__device__ float g_pooled[(size_t)BB * DD];
__device__ int   g_cnt[BB];

// ---------------- embed: h = x_emb1[x[:,0]] + x_emb2[x[:,1]] ----------------
__global__ void embed_kernel(const int* __restrict__ x,
                             const float* __restrict__ e1,
                             const float* __restrict__ e2,
                             float* __restrict__ h, int n)
{
    int idx = blockIdx.x * blockDim.x + threadIdx.x;
    int total = n * DD;
    if (idx >= total) return;
    int row = idx / DD;
    int d = idx - row * DD;
    int a = x[row * 2];
    int c = x[row * 2 + 1];
    h[idx] = e1[(size_t)a * DD + d] + e2[(size_t)c * DD + d];
}

// ---------------- init agg = h + self_e; also zero BN stats ----------------
__global__ void init_agg_kernel(const float* __restrict__ h,
                                const float* __restrict__ e1l,   // edge_emb1[l] (5 x D)
                                const float* __restrict__ e2l,   // edge_emb2[l] (3 x D)
                                float* __restrict__ agg,
                                float* __restrict__ stats, int n)
{
    int idx = blockIdx.x * blockDim.x + threadIdx.x;
    if (idx < 2 * DD) stats[idx] = 0.0f;
    int total = n * DD;
    if (idx >= total) return;
    int d = idx & (DD - 1);
    float self_e = e1l[4 * DD + d] + e2l[d];
    agg[idx] = h[idx] + self_e;
}

// ---------------- scatter: agg[dst] += h[src] + e(bt,bd)  (warp per edge) ---
__global__ void scatter_kernel(const int* __restrict__ ei,
                               const int* __restrict__ ea,
                               const float* __restrict__ e1l,
                               const float* __restrict__ e2l,
                               const float* __restrict__ h,
                               float* __restrict__ agg, int e_cnt)
{
    int gw = (blockIdx.x * blockDim.x + threadIdx.x) >> 5;
    int lane = threadIdx.x & 31;
    if (gw >= e_cnt) return;
    int src = ei[gw];
    int dst = ei[e_cnt + gw];
    int bt = ea[2 * gw];
    int bd = ea[2 * gw + 1];
    const float* hv = h + (size_t)src * DD;
    const float* t1 = e1l + (size_t)bt * DD;
    const float* t2 = e2l + (size_t)bd * DD;
    float* av = agg + (size_t)dst * DD;
#pragma unroll
    for (int d = lane; d < DD; d += 32) {
        atomicAdd(&av[d], hv[d] + t1[d] + t2[d]);
    }
}

// ---------------- tf32 tensor-core GEMM: C = act(A @ B + bias) --------------
// A: M x K row-major, B: K x Nc row-major, C: M x Nc. 256 threads/block.
// Block tile 128x128x16; 8 warps in 2(m) x 4(n); warp tile 64x32 of
// m16n8k8 tf32 MMAs. Smem strides chosen for conflict-free fragment LDS:
//   A stride 20 floats: banks (20*g + c) mod 32 all distinct over g=0..7,c=0..3
//   B stride 136 floats: banks (8*c + g) mod 32 cover all 32 banks
#define TBM 128
#define TBN 128
#define TBK 16
#define ASTRIDE 20
#define BSTRIDE 136

__device__ __forceinline__ unsigned f2tf(float x)
{
    unsigned r;
    asm("cvt.rna.tf32.f32 %0, %1;" : "=r"(r) : "f"(x));
    return r;
}

template<bool RELU>
__global__ __launch_bounds__(256, 2)
void mma_gemm_kernel(int M, int Nc, int K,
                     const float* __restrict__ A,
                     const float* __restrict__ B,
                     const float* __restrict__ bias,
                     float* __restrict__ C)
{
    __shared__ unsigned As[TBM * ASTRIDE];
    __shared__ unsigned Bs[TBK * BSTRIDE];

    const int tid  = threadIdx.x;
    const int warp = tid >> 5;
    const int lane = tid & 31;
    const int gr   = lane >> 2;   // 0..7
    const int cq   = lane & 3;    // 0..3

    const int wm = (warp & 1) * 64;    // warp row offset in tile
    const int wn = (warp >> 1) * 32;   // warp col offset in tile

    const int bm = blockIdx.y * TBM;
    const int bn = blockIdx.x * TBN;

    float acc[4][4][4];
#pragma unroll
    for (int mi = 0; mi < 4; mi++)
#pragma unroll
        for (int ni = 0; ni < 4; ni++)
#pragma unroll
            for (int q = 0; q < 4; q++) acc[mi][ni][q] = 0.0f;

    for (int k0 = 0; k0 < K; k0 += TBK) {
        // ---- A tile: 128 rows x 16 cols. 512 float4 loads, 2 per thread ----
#pragma unroll
        for (int i = 0; i < 2; i++) {
            int v   = tid + i * 256;
            int row = v >> 2;            // 0..127
            int c4  = (v & 3) << 2;      // 0,4,8,12
            float4 f = make_float4(0.f, 0.f, 0.f, 0.f);
            if (bm + row < M)
                f = *reinterpret_cast<const float4*>(
                        A + (size_t)(bm + row) * K + k0 + c4);
            uint4 t;
            t.x = f2tf(f.x); t.y = f2tf(f.y); t.z = f2tf(f.z); t.w = f2tf(f.w);
            *reinterpret_cast<uint4*>(&As[row * ASTRIDE + c4]) = t;
        }
        // ---- B tile: 16 rows x 128 cols. 512 float4 loads, 2 per thread ----
#pragma unroll
        for (int i = 0; i < 2; i++) {
            int v   = tid + i * 256;
            int row = v >> 5;            // 0..15
            int c4  = (v & 31) << 2;     // 0..124
            float4 f = *reinterpret_cast<const float4*>(
                           B + (size_t)(k0 + row) * Nc + bn + c4);
            uint4 t;
            t.x = f2tf(f.x); t.y = f2tf(f.y); t.z = f2tf(f.z); t.w = f2tf(f.w);
            *reinterpret_cast<uint4*>(&Bs[row * BSTRIDE + c4]) = t;
        }
        __syncthreads();

#pragma unroll
        for (int ks = 0; ks < TBK; ks += 8) {
            unsigned af[4][4], bf[4][2];
#pragma unroll
            for (int mi = 0; mi < 4; mi++) {
                int r = wm + mi * 16 + gr;
                af[mi][0] = As[r * ASTRIDE + ks + cq];
                af[mi][1] = As[(r + 8) * ASTRIDE + ks + cq];
                af[mi][2] = As[r * ASTRIDE + ks + cq + 4];
                af[mi][3] = As[(r + 8) * ASTRIDE + ks + cq + 4];
            }
#pragma unroll
            for (int ni = 0; ni < 4; ni++) {
                int cl = wn + ni * 8 + gr;
                bf[ni][0] = Bs[(ks + cq) * BSTRIDE + cl];
                bf[ni][1] = Bs[(ks + cq + 4) * BSTRIDE + cl];
            }
#pragma unroll
            for (int mi = 0; mi < 4; mi++)
#pragma unroll
                for (int ni = 0; ni < 4; ni++)
                    asm volatile(
                        "mma.sync.aligned.m16n8k8.row.col.f32.tf32.tf32.f32 "
                        "{%0,%1,%2,%3}, {%4,%5,%6,%7}, {%8,%9}, {%0,%1,%2,%3};"
                        : "+f"(acc[mi][ni][0]), "+f"(acc[mi][ni][1]),
                          "+f"(acc[mi][ni][2]), "+f"(acc[mi][ni][3])
                        : "r"(af[mi][0]), "r"(af[mi][1]),
                          "r"(af[mi][2]), "r"(af[mi][3]),
                          "r"(bf[ni][0]), "r"(bf[ni][1]));
        }
        __syncthreads();
    }

    // ---- epilogue: bias (+relu), direct float2 stores ----
#pragma unroll
    for (int mi = 0; mi < 4; mi++) {
        int r0 = bm + wm + mi * 16 + gr;
#pragma unroll
        for (int ni = 0; ni < 4; ni++) {
            int col = bn + wn + ni * 8 + cq * 2;
            float bz0 = bias[col];
            float bz1 = bias[col + 1];
            float v0 = acc[mi][ni][0] + bz0;
            float v1 = acc[mi][ni][1] + bz1;
            float v2 = acc[mi][ni][2] + bz0;
            float v3 = acc[mi][ni][3] + bz1;
            if (RELU) {
                v0 = fmaxf(v0, 0.f); v1 = fmaxf(v1, 0.f);
                v2 = fmaxf(v2, 0.f); v3 = fmaxf(v3, 0.f);
            }
            if (r0 < M) {
                float2 w0 = make_float2(v0, v1);
                *reinterpret_cast<float2*>(C + (size_t)r0 * Nc + col) = w0;
            }
            if (r0 + 8 < M) {
                float2 w1 = make_float2(v2, v3);
                *reinterpret_cast<float2*>(C + (size_t)(r0 + 8) * Nc + col) = w1;
            }
        }
    }
}

// ---------------- BN column stats: sums / sumsq per column ------------------
__global__ void stats_kernel(const float* __restrict__ z,
                             float* __restrict__ stats, int n)
{
    int d = threadIdx.x;   // 256 threads = 256 columns
    float s = 0.f, s2 = 0.f;
    for (int r = blockIdx.x; r < n; r += gridDim.x) {
        float v = z[(size_t)r * DD + d];
        s += v;
        s2 += v * v;
    }
    atomicAdd(&stats[d], s);
    atomicAdd(&stats[DD + d], s2);
}

// ---------------- BN normalize + relu -> h ---------------------------------
__global__ void bn_relu_kernel(const float* __restrict__ z,
                               const float* __restrict__ stats,
                               const float* __restrict__ g,
                               const float* __restrict__ b,
                               float* __restrict__ h, int n)
{
    int idx = blockIdx.x * blockDim.x + threadIdx.x;
    int total = n * DD;
    if (idx >= total) return;
    int d = idx & (DD - 1);
    float invn = 1.0f / (float)n;
    float mu = stats[d] * invn;
    float var = stats[DD + d] * invn - mu * mu;
    float inv = rsqrtf(var + 1e-5f);
    float v = (z[idx] - mu) * inv * g[d] + b[d];
    h[idx] = fmaxf(v, 0.f);
}

// ---------------- pooling ---------------------------------------------------
__global__ void zero_pool_kernel(float* __restrict__ pooled, int* __restrict__ cnt)
{
    int idx = blockIdx.x * blockDim.x + threadIdx.x;
    if (idx < BB * DD) pooled[idx] = 0.f;
    if (idx < BB) cnt[idx] = 0;
}

__global__ void pool_cnt_kernel(const int* __restrict__ batch, int* __restrict__ cnt, int n)
{
    int i = blockIdx.x * blockDim.x + threadIdx.x;
    if (i < n) atomicAdd(&cnt[batch[i]], 1);
}

__global__ void pool_sum_kernel(const float* __restrict__ h,
                                const int* __restrict__ batch,
                                float* __restrict__ pooled, int n)
{
    int idx = blockIdx.x * blockDim.x + threadIdx.x;
    int total = n * DD;
    if (idx >= total) return;
    int row = idx / DD;
    int d = idx - row * DD;
    int g = batch[row];
    atomicAdd(&pooled[(size_t)g * DD + d], h[idx]);
}

// ---------------- head: softplus(pooled/cnt @ Wo1 + bo1) @ Wo2 + bo2 --------
__global__ void head_kernel(const float* __restrict__ pooled,
                            const int* __restrict__ cnt,
                            const float* __restrict__ Wo1,
                            const float* __restrict__ bo1,
                            const float* __restrict__ Wo2,
                            const float* __restrict__ bo2,
                            float* __restrict__ out)
{
    __shared__ float p[DD];
    __shared__ float r0[128];
    __shared__ float r1[128];
    int g = blockIdx.x;
    int t = threadIdx.x;   // 128 threads
    float inv = 1.0f / fmaxf((float)cnt[g], 1.0f);
    p[t]        = pooled[(size_t)g * DD + t] * inv;
    p[t + 128]  = pooled[(size_t)g * DD + t + 128] * inv;
    __syncthreads();

    float acc = bo1[t];
#pragma unroll 8
    for (int k = 0; k < DD; k++)
        acc = fmaf(p[k], Wo1[k * 128 + t], acc);

    // numerically-stable softplus
    float sp = (acc > 0.f) ? (acc + log1pf(expf(-acc))) : log1pf(expf(acc));

    r0[t] = sp * Wo2[t * 2 + 0];
    r1[t] = sp * Wo2[t * 2 + 1];
    __syncthreads();
    for (int s = 64; s > 0; s >>= 1) {
        if (t < s) { r0[t] += r0[t + s]; r1[t] += r1[t + s]; }
        __syncthreads();
    }
    if (t == 0) {
        out[g * 2 + 0] = r0[0] + bo2[0];
        out[g * 2 + 1] = r1[0] + bo2[1];
    }
}

// ---------------- launch ----------------------------------------------------
extern "C" void kernel_launch(void* const* d_in, const int* in_sizes, int n_in,
                              void* d_out, int out_size)
{
    const int*   x         = (const int*)d_in[0];
    const int*   ei        = (const int*)d_in[1];
    const int*   ea        = (const int*)d_in[2];
    const int*   batch     = (const int*)d_in[3];
    const float* x_emb1    = (const float*)d_in[4];
    const float* x_emb2    = (const float*)d_in[5];
    const float* edge_emb1 = (const float*)d_in[6];   // (5, 5, 256)
    const float* edge_emb2 = (const float*)d_in[7];   // (5, 3, 256)
    const float* W1        = (const float*)d_in[8];   // (5, 256, 512)
    const float* b1        = (const float*)d_in[9];   // (5, 512)
    const float* W2        = (const float*)d_in[10];  // (5, 512, 256)
    const float* b2        = (const float*)d_in[11];  // (5, 256)
    const float* bn_g      = (const float*)d_in[12];  // (5, 256)
    const float* bn_b      = (const float*)d_in[13];  // (5, 256)
    const float* Wo1       = (const float*)d_in[14];  // (256, 128)
    const float* bo1       = (const float*)d_in[15];
    const float* Wo2       = (const float*)d_in[16];  // (128, 2)
    const float* bo2       = (const float*)d_in[17];
    float* out = (float*)d_out;

    const int n = in_sizes[0] / 2;   // 100000
    const int e = in_sizes[1] / 2;   // 200000

    float* h      = nullptr;
    float* agg    = nullptr;
    float* z1     = nullptr;
    float* z      = nullptr;
    float* stats  = nullptr;
    float* pooled = nullptr;
    int*   cnt    = nullptr;
    cudaGetSymbolAddress((void**)&h,      g_h);
    cudaGetSymbolAddress((void**)&agg,    g_agg);
    cudaGetSymbolAddress((void**)&z1,     g_z1);
    cudaGetSymbolAddress((void**)&z,      g_z);
    cudaGetSymbolAddress((void**)&stats,  g_stats);
    cudaGetSymbolAddress((void**)&pooled, g_pooled);
    cudaGetSymbolAddress((void**)&cnt,    g_cnt);

    const int TPB = 256;
    const int totND = n * DD;
    const int gND = (totND + TPB - 1) / TPB;

    embed_kernel<<<gND, TPB>>>(x, x_emb1, x_emb2, h, n);

    for (int l = 0; l < LL; l++) {
        const float* e1l = edge_emb1 + (size_t)l * 5 * DD;
        const float* e2l = edge_emb2 + (size_t)l * 3 * DD;
        const float* W1l = W1 + (size_t)l * DD * 2 * DD;
        const float* b1l = b1 + (size_t)l * 2 * DD;
        const float* W2l = W2 + (size_t)l * 2 * DD * DD;
        const float* b2l = b2 + (size_t)l * DD;
        const float* gl  = bn_g + (size_t)l * DD;
        const float* bl  = bn_b + (size_t)l * DD;

        init_agg_kernel<<<gND, TPB>>>(h, e1l, e2l, agg, stats, n);

        int scatterBlocks = (e * 32 + TPB - 1) / TPB;
        scatter_kernel<<<scatterBlocks, TPB>>>(ei, ea, e1l, e2l, h, agg, e);

        // GEMM1: z1 = relu(agg @ W1l + b1l)   (n x 512)
        {
            dim3 grid(2 * DD / TBN, (n + TBM - 1) / TBM);
            mma_gemm_kernel<true><<<grid, 256>>>(n, 2 * DD, DD, agg, W1l, b1l, z1);
        }
        // GEMM2: z = z1 @ W2l + b2l           (n x 256)
        {
            dim3 grid(DD / TBN, (n + TBM - 1) / TBM);
            mma_gemm_kernel<false><<<grid, 256>>>(n, DD, 2 * DD, z1, W2l, b2l, z);
        }

        stats_kernel<<<512, DD>>>(z, stats, n);
        bn_relu_kernel<<<gND, TPB>>>(z, stats, gl, bl, h, n);
    }

    zero_pool_kernel<<<(BB * DD + TPB - 1) / TPB, TPB>>>(pooled, cnt);
    pool_cnt_kernel<<<(n + TPB - 1) / TPB, TPB>>>(batch, cnt, n);
    pool_sum_kernel<<<gND, TPB>>>(h, batch, pooled, n);
    head_kernel<<<BB, 128>>>(pooled, cnt, Wo1, bo1, Wo2, bo2, out);
}